// round 1
// baseline (speedup 1.0000x reference)
#include <cuda_runtime.h>
#include <cuda_bf16.h>
#include <math.h>

// ---------------- problem constants ----------------
#define BATCH    2
#define SEQ      1024
#define DMODEL   2048
#define DINNER   4096
#define DSTATE   16
#define DCONV    4
#define DTRANK   128
#define XDBL_W   (DTRANK + 2*DSTATE)   // 160
#define MROWS    (BATCH*SEQ)           // 2048

// ---------------- device scratch (allocation-free rule: __device__ globals) ----------------
__device__ float g_xz   [(size_t)MROWS * (2*DINNER)]; // 2048 x 8192 (x-pre-conv | z)
__device__ float g_x    [(size_t)MROWS * DINNER];     // post conv+silu
__device__ float g_xdbl [(size_t)MROWS * XDBL_W];     // dt_low | B | C
__device__ float g_delta[(size_t)MROWS * DINNER];     // softplus(dt + b_dt)
__device__ float g_y    [(size_t)MROWS * DINNER];     // gated scan output

// ---------------- generic SGEMM: C[M,N] = A[M,K] * B[N,K]^T (both row-major, K contiguous) ----------------
// BM=BN=128, BK=8, 256 threads, 8x8 per-thread tile.
// mode 0: plain store.  mode 1: C = softplus(acc + bias[col])
__global__ void sgemm_nt(const float* __restrict__ A, int lda,
                         const float* __restrict__ B, int ldb,
                         float* __restrict__ C, int ldc,
                         int M, int N, int K,
                         int mode, const float* __restrict__ bias)
{
    __shared__ float As[8][128];
    __shared__ float Bs[8][128];

    const int tid  = threadIdx.x;          // 0..255
    const int brow = blockIdx.y * 128;
    const int bcol = blockIdx.x * 128;
    const int ty   = tid >> 4;              // 0..15
    const int tx   = tid & 15;              // 0..15

    const int lrow = tid >> 1;              // 0..127
    const int kseg = (tid & 1) * 4;         // 0 or 4

    float acc[8][8];
#pragma unroll
    for (int i = 0; i < 8; i++)
#pragma unroll
        for (int j = 0; j < 8; j++) acc[i][j] = 0.f;

    for (int kk = 0; kk < K; kk += 8) {
        float4 av = make_float4(0.f, 0.f, 0.f, 0.f);
        int ar = brow + lrow;
        if (ar < M)
            av = *reinterpret_cast<const float4*>(A + (size_t)ar * lda + kk + kseg);
        As[kseg + 0][lrow] = av.x;
        As[kseg + 1][lrow] = av.y;
        As[kseg + 2][lrow] = av.z;
        As[kseg + 3][lrow] = av.w;

        float4 bv = make_float4(0.f, 0.f, 0.f, 0.f);
        int bc = bcol + lrow;
        if (bc < N)
            bv = *reinterpret_cast<const float4*>(B + (size_t)bc * ldb + kk + kseg);
        Bs[kseg + 0][lrow] = bv.x;
        Bs[kseg + 1][lrow] = bv.y;
        Bs[kseg + 2][lrow] = bv.z;
        Bs[kseg + 3][lrow] = bv.w;

        __syncthreads();

#pragma unroll
        for (int k = 0; k < 8; k++) {
            float a[8], b[8];
#pragma unroll
            for (int i = 0; i < 8; i++) a[i] = As[k][ty * 8 + i];
#pragma unroll
            for (int j = 0; j < 8; j++) b[j] = Bs[k][tx * 8 + j];
#pragma unroll
            for (int i = 0; i < 8; i++)
#pragma unroll
                for (int j = 0; j < 8; j++)
                    acc[i][j] = fmaf(a[i], b[j], acc[i][j]);
        }
        __syncthreads();
    }

#pragma unroll
    for (int i = 0; i < 8; i++) {
        int row = brow + ty * 8 + i;
        if (row >= M) continue;
#pragma unroll
        for (int j = 0; j < 8; j++) {
            int col = bcol + tx * 8 + j;
            if (col >= N) continue;
            float v = acc[i][j];
            if (mode == 1) {
                v += bias[col];
                // numerically stable softplus
                v = fmaxf(v, 0.f) + log1pf(expf(-fabsf(v)));
            }
            C[(size_t)row * ldc + col] = v;
        }
    }
}

// ---------------- causal depthwise conv1d (K=4) + SiLU ----------------
// reads x-half of g_xz (cols [0, DINNER)), writes g_x
__global__ void conv_silu_kernel(const float* __restrict__ conv_w,
                                 const float* __restrict__ conv_b)
{
    int d = blockIdx.x * 256 + threadIdx.x;   // 0..4095
    int m = blockIdx.y;                       // 0..2047 (b*SEQ + l)
    int b = m >> 10;
    int l = m & (SEQ - 1);

    float acc = conv_b[d];
#pragma unroll
    for (int k = 0; k < DCONV; k++) {
        int lk = l - (DCONV - 1) + k;
        if (lk >= 0)
            acc = fmaf(conv_w[d * DCONV + k],
                       g_xz[(size_t)(b * SEQ + lk) * (2 * DINNER) + d], acc);
    }
    float s = acc / (1.f + __expf(-acc));     // silu
    g_x[(size_t)m * DINNER + d] = s;
}

// ---------------- selective scan, fused skip + gate ----------------
// one thread per (b, d); 16 states in registers; 32-step chunks staged in smem
__global__ void scan_kernel(const float* __restrict__ A_log,
                            const float* __restrict__ D_skip)
{
    __shared__ float s_delta[32][64];
    __shared__ float s_u[32][64];
    __shared__ float s_z[32][64];
    __shared__ float s_bc[32][32];   // [t][0:16)=B, [t][16:32)=C

    const int tid   = threadIdx.x;                 // 0..63
    const int bpb   = DINNER / 64;                 // 64 blocks per batch
    const int b     = blockIdx.x / bpb;
    const int dbase = (blockIdx.x % bpb) * 64;
    const int d     = dbase + tid;

    float Arow[DSTATE];
#pragma unroll
    for (int n = 0; n < DSTATE; n++)
        Arow[n] = -__expf(A_log[(size_t)d * DSTATE + n]);
    const float Dv = D_skip[d];

    float h[DSTATE];
#pragma unroll
    for (int n = 0; n < DSTATE; n++) h[n] = 0.f;

    for (int l0 = 0; l0 < SEQ; l0 += 32) {
        // cooperative staging (coalesced)
#pragma unroll 4
        for (int t = 0; t < 32; t++) {
            size_t row = (size_t)(b * SEQ + l0 + t);
            s_delta[t][tid] = g_delta[row * DINNER + d];
            s_u[t][tid]     = g_x[row * DINNER + d];
            s_z[t][tid]     = g_xz[row * (2 * DINNER) + DINNER + d];
        }
        for (int i = tid; i < 32 * 32; i += 64) {
            int t = i >> 5, j = i & 31;
            s_bc[t][j] = g_xdbl[(size_t)(b * SEQ + l0 + t) * XDBL_W + DTRANK + j];
        }
        __syncthreads();

        for (int t = 0; t < 32; t++) {
            float delta = s_delta[t][tid];
            float u     = s_u[t][tid];
            float du    = delta * u;
            float y     = 0.f;
#pragma unroll
            for (int n = 0; n < DSTATE; n++) {
                float dA = __expf(delta * Arow[n]);
                h[n] = fmaf(h[n], dA, du * s_bc[t][n]);
                y    = fmaf(h[n], s_bc[t][DSTATE + n], y);
            }
            float zz = s_z[t][tid];
            float gate = zz / (1.f + __expf(-zz));     // silu(z)
            float out  = (y + Dv * u) * gate;
            g_y[(size_t)(b * SEQ + l0 + t) * DINNER + d] = out;
        }
        __syncthreads();
    }
}

// ---------------- launcher ----------------
extern "C" void kernel_launch(void* const* d_in, const int* in_sizes, int n_in,
                              void* d_out, int out_size)
{
    const float* hidden = (const float*)d_in[0];  // (B, L, DMODEL)
    const float* W_in   = (const float*)d_in[1];  // (2*Di, DMODEL)
    const float* conv_w = (const float*)d_in[2];  // (Di, 4)
    const float* conv_b = (const float*)d_in[3];  // (Di,)
    const float* W_x    = (const float*)d_in[4];  // (160, Di)
    const float* W_dt   = (const float*)d_in[5];  // (Di, 128)
    const float* b_dt   = (const float*)d_in[6];  // (Di,)
    const float* A_log  = (const float*)d_in[7];  // (Di, 16)
    const float* D_skip = (const float*)d_in[8];  // (Di,)
    const float* W_out  = (const float*)d_in[9];  // (DMODEL, Di)
    float* out = (float*)d_out;                   // (B, L, DMODEL)

    float *xz, *x, *xdbl, *delta, *y;
    cudaGetSymbolAddress((void**)&xz,    g_xz);
    cudaGetSymbolAddress((void**)&x,     g_x);
    cudaGetSymbolAddress((void**)&xdbl,  g_xdbl);
    cudaGetSymbolAddress((void**)&delta, g_delta);
    cudaGetSymbolAddress((void**)&y,     g_y);

    dim3 blk(256);

    // 1) xz = hidden @ W_in^T   (2048 x 8192, K=2048)
    sgemm_nt<<<dim3((2*DINNER)/128, MROWS/128), blk>>>(
        hidden, DMODEL, W_in, DMODEL, xz, 2*DINNER,
        MROWS, 2*DINNER, DMODEL, 0, nullptr);

    // 2) causal conv + silu -> g_x
    conv_silu_kernel<<<dim3(DINNER/256, MROWS), 256>>>(conv_w, conv_b);

    // 3) x_dbl = x @ W_x^T      (2048 x 160, K=4096)
    sgemm_nt<<<dim3((XDBL_W + 127)/128, MROWS/128), blk>>>(
        x, DINNER, W_x, DINNER, xdbl, XDBL_W,
        MROWS, XDBL_W, DINNER, 0, nullptr);

    // 4) delta = softplus(dt_low @ W_dt^T + b_dt)   (2048 x 4096, K=128; A has lda=160)
    sgemm_nt<<<dim3(DINNER/128, MROWS/128), blk>>>(
        xdbl, XDBL_W, W_dt, DTRANK, delta, DINNER,
        MROWS, DINNER, DTRANK, 1, b_dt);

    // 5) selective scan + skip + gating -> g_y
    scan_kernel<<<BATCH * (DINNER/64), 64>>>(A_log, D_skip);

    // 6) out = y @ W_out^T      (2048 x 2048, K=4096)
    sgemm_nt<<<dim3(DMODEL/128, MROWS/128), blk>>>(
        y, DINNER, W_out, DINNER, out, DMODEL,
        MROWS, DMODEL, DINNER, 0, nullptr);
}

// round 2
// speedup vs baseline: 2.2789x; 2.2789x over previous
#include <cuda_runtime.h>
#include <cuda_bf16.h>
#include <math.h>
#include <stdint.h>

// ---------------- problem constants ----------------
#define BATCH    2
#define SEQ      1024
#define DMODEL   2048
#define DINNER   4096
#define DSTATE   16
#define DCONV    4
#define DTRANK   128
#define XDBL_W   (DTRANK + 2*DSTATE)   // 160
#define MROWS    (BATCH*SEQ)           // 2048

// ---------------- device scratch ----------------
__device__ float g_xz   [(size_t)MROWS * (2*DINNER)];
__device__ float g_x    [(size_t)MROWS * DINNER];
__device__ float g_xdbl [(size_t)MROWS * XDBL_W];
__device__ float g_delta[(size_t)MROWS * DINNER];
__device__ float g_y    [(size_t)MROWS * DINNER];

// ---------------- helpers ----------------
__device__ __forceinline__ uint32_t f2tf32(float f) {
    uint32_t r;
    asm("cvt.rna.tf32.f32 %0, %1;" : "=r"(r) : "f"(f));
    return r;
}

__device__ __forceinline__ void mma_tf32(float* c,
    uint32_t a0, uint32_t a1, uint32_t a2, uint32_t a3,
    uint32_t b0, uint32_t b1)
{
    asm volatile(
        "mma.sync.aligned.m16n8k8.row.col.f32.tf32.tf32.f32 "
        "{%0,%1,%2,%3}, {%4,%5,%6,%7}, {%8,%9}, {%0,%1,%2,%3};"
        : "+f"(c[0]), "+f"(c[1]), "+f"(c[2]), "+f"(c[3])
        : "r"(a0), "r"(a1), "r"(a2), "r"(a3), "r"(b0), "r"(b1));
}

// ---------------- TF32 tensor-core GEMM: C[M,N] = A[M,K] * B[N,K]^T ----------------
// BM=BN=128, BK=16, 256 threads (8 warps, 2x4 -> warp tile 64x32).
// mode 0: plain store.  mode 1: C = softplus(acc + bias[col])
// Requires: M % 128 == 0, K % 16 == 0. N may be ragged (guarded).
__global__ __launch_bounds__(256, 2)
void tf32_gemm_nt(const float* __restrict__ A, int lda,
                  const float* __restrict__ B, int ldb,
                  float* __restrict__ C, int ldc,
                  int M, int N, int K,
                  int mode, const float* __restrict__ bias)
{
    __shared__ uint32_t As[2][16][136];   // [buf][k][m], pad 8 -> conflict-free frag reads
    __shared__ uint32_t Bs[2][16][136];   // [buf][k][n]

    const int tid  = threadIdx.x;
    const int lane = tid & 31;
    const int w    = tid >> 5;
    const int wm   = (w & 1) * 64;    // warp m-offset in tile
    const int wn   = (w >> 1) * 32;   // warp n-offset in tile
    const int brow = blockIdx.y * 128;
    const int bcol = blockIdx.x * 128;

    const int lr = lane >> 2;   // 0..7
    const int lc = lane & 3;    // 0..3

    float acc[4][4][4];
#pragma unroll
    for (int mt = 0; mt < 4; mt++)
#pragma unroll
        for (int nt = 0; nt < 4; nt++)
#pragma unroll
            for (int r = 0; r < 4; r++) acc[mt][nt][r] = 0.f;

    // staging: each thread handles 2 float4 per tile per matrix
    // linear = tid + 256*t : row = linear>>2 (0..127), seg = linear&3 (k-quad)
    float4 ra[2], rb[2];

    const int T = K >> 4;

    // ---- prefetch tile 0 into regs, store to buf 0 ----
#pragma unroll
    for (int t = 0; t < 2; t++) {
        int linear = tid + 256 * t;
        int row = linear >> 2, seg = linear & 3;
        ra[t] = *reinterpret_cast<const float4*>(A + (size_t)(brow + row) * lda + seg * 4);
        int bc = bcol + row;
        if (bc < N)
            rb[t] = *reinterpret_cast<const float4*>(B + (size_t)bc * ldb + seg * 4);
        else
            rb[t] = make_float4(0.f, 0.f, 0.f, 0.f);
    }
#pragma unroll
    for (int t = 0; t < 2; t++) {
        int linear = tid + 256 * t;
        int row = linear >> 2, seg = linear & 3;
        As[0][seg * 4 + 0][row] = f2tf32(ra[t].x);
        As[0][seg * 4 + 1][row] = f2tf32(ra[t].y);
        As[0][seg * 4 + 2][row] = f2tf32(ra[t].z);
        As[0][seg * 4 + 3][row] = f2tf32(ra[t].w);
        Bs[0][seg * 4 + 0][row] = f2tf32(rb[t].x);
        Bs[0][seg * 4 + 1][row] = f2tf32(rb[t].y);
        Bs[0][seg * 4 + 2][row] = f2tf32(rb[t].z);
        Bs[0][seg * 4 + 3][row] = f2tf32(rb[t].w);
    }
    __syncthreads();

    for (int it = 0; it < T; it++) {
        const int cur = it & 1;
        const bool pf = (it + 1 < T);

        // ---- issue global loads for next tile (latency overlaps MMA) ----
        if (pf) {
            int kk = (it + 1) << 4;
#pragma unroll
            for (int t = 0; t < 2; t++) {
                int linear = tid + 256 * t;
                int row = linear >> 2, seg = linear & 3;
                ra[t] = *reinterpret_cast<const float4*>(A + (size_t)(brow + row) * lda + kk + seg * 4);
                int bc = bcol + row;
                if (bc < N)
                    rb[t] = *reinterpret_cast<const float4*>(B + (size_t)bc * ldb + kk + seg * 4);
                else
                    rb[t] = make_float4(0.f, 0.f, 0.f, 0.f);
            }
        }

        // ---- compute on current buffer ----
#pragma unroll
        for (int ks = 0; ks < 16; ks += 8) {
            uint32_t af[4][4], bf[4][2];
#pragma unroll
            for (int mt = 0; mt < 4; mt++) {
                int r0 = wm + mt * 16 + lr;
                af[mt][0] = As[cur][ks + lc    ][r0];
                af[mt][1] = As[cur][ks + lc    ][r0 + 8];
                af[mt][2] = As[cur][ks + 4 + lc][r0];
                af[mt][3] = As[cur][ks + 4 + lc][r0 + 8];
            }
#pragma unroll
            for (int nt = 0; nt < 4; nt++) {
                int c0 = wn + nt * 8 + lr;
                bf[nt][0] = Bs[cur][ks + lc    ][c0];
                bf[nt][1] = Bs[cur][ks + 4 + lc][c0];
            }
#pragma unroll
            for (int mt = 0; mt < 4; mt++)
#pragma unroll
                for (int nt = 0; nt < 4; nt++)
                    mma_tf32(acc[mt][nt], af[mt][0], af[mt][1], af[mt][2], af[mt][3],
                             bf[nt][0], bf[nt][1]);
        }

        // ---- commit prefetched tile to other buffer ----
        if (pf) {
            int nxt = cur ^ 1;
#pragma unroll
            for (int t = 0; t < 2; t++) {
                int linear = tid + 256 * t;
                int row = linear >> 2, seg = linear & 3;
                As[nxt][seg * 4 + 0][row] = f2tf32(ra[t].x);
                As[nxt][seg * 4 + 1][row] = f2tf32(ra[t].y);
                As[nxt][seg * 4 + 2][row] = f2tf32(ra[t].z);
                As[nxt][seg * 4 + 3][row] = f2tf32(ra[t].w);
                Bs[nxt][seg * 4 + 0][row] = f2tf32(rb[t].x);
                Bs[nxt][seg * 4 + 1][row] = f2tf32(rb[t].y);
                Bs[nxt][seg * 4 + 2][row] = f2tf32(rb[t].z);
                Bs[nxt][seg * 4 + 3][row] = f2tf32(rb[t].w);
            }
        }
        __syncthreads();
    }

    // ---- epilogue ----
#pragma unroll
    for (int mt = 0; mt < 4; mt++) {
#pragma unroll
        for (int nt = 0; nt < 4; nt++) {
#pragma unroll
            for (int r = 0; r < 4; r++) {
                int row = brow + wm + mt * 16 + lr + ((r & 2) ? 8 : 0);
                int col = bcol + wn + nt * 8 + 2 * lc + (r & 1);
                if (col >= N) continue;
                float v = acc[mt][nt][r];
                if (mode == 1) {
                    v += bias[col];
                    v = fmaxf(v, 0.f) + log1pf(expf(-fabsf(v)));
                }
                C[(size_t)row * ldc + col] = v;
            }
        }
    }
}

// ---------------- causal depthwise conv1d (K=4) + SiLU ----------------
__global__ void conv_silu_kernel(const float* __restrict__ conv_w,
                                 const float* __restrict__ conv_b)
{
    int d = blockIdx.x * 256 + threadIdx.x;
    int m = blockIdx.y;
    int b = m >> 10;
    int l = m & (SEQ - 1);

    float acc = conv_b[d];
#pragma unroll
    for (int k = 0; k < DCONV; k++) {
        int lk = l - (DCONV - 1) + k;
        if (lk >= 0)
            acc = fmaf(conv_w[d * DCONV + k],
                       g_xz[(size_t)(b * SEQ + lk) * (2 * DINNER) + d], acc);
    }
    float s = acc / (1.f + __expf(-acc));
    g_x[(size_t)m * DINNER + d] = s;
}

// ---------------- selective scan, fused skip + gate ----------------
__global__ void scan_kernel(const float* __restrict__ A_log,
                            const float* __restrict__ D_skip)
{
    __shared__ float s_delta[32][64];
    __shared__ float s_u[32][64];
    __shared__ float s_z[32][64];
    __shared__ float s_bc[32][32];

    const int tid   = threadIdx.x;
    const int bpb   = DINNER / 64;
    const int b     = blockIdx.x / bpb;
    const int dbase = (blockIdx.x % bpb) * 64;
    const int d     = dbase + tid;

    float Arow[DSTATE];
#pragma unroll
    for (int n = 0; n < DSTATE; n++)
        Arow[n] = -__expf(A_log[(size_t)d * DSTATE + n]);
    const float Dv = D_skip[d];

    float h[DSTATE];
#pragma unroll
    for (int n = 0; n < DSTATE; n++) h[n] = 0.f;

    for (int l0 = 0; l0 < SEQ; l0 += 32) {
#pragma unroll 4
        for (int t = 0; t < 32; t++) {
            size_t row = (size_t)(b * SEQ + l0 + t);
            s_delta[t][tid] = g_delta[row * DINNER + d];
            s_u[t][tid]     = g_x[row * DINNER + d];
            s_z[t][tid]     = g_xz[row * (2 * DINNER) + DINNER + d];
        }
        for (int i = tid; i < 32 * 32; i += 64) {
            int t = i >> 5, j = i & 31;
            s_bc[t][j] = g_xdbl[(size_t)(b * SEQ + l0 + t) * XDBL_W + DTRANK + j];
        }
        __syncthreads();

        for (int t = 0; t < 32; t++) {
            float delta = s_delta[t][tid];
            float u     = s_u[t][tid];
            float du    = delta * u;
            float y     = 0.f;
#pragma unroll
            for (int n = 0; n < DSTATE; n++) {
                float dA = __expf(delta * Arow[n]);
                h[n] = fmaf(h[n], dA, du * s_bc[t][n]);
                y    = fmaf(h[n], s_bc[t][DSTATE + n], y);
            }
            float zz = s_z[t][tid];
            float gate = zz / (1.f + __expf(-zz));
            float out  = (y + Dv * u) * gate;
            g_y[(size_t)(b * SEQ + l0 + t) * DINNER + d] = out;
        }
        __syncthreads();
    }
}

// ---------------- launcher ----------------
extern "C" void kernel_launch(void* const* d_in, const int* in_sizes, int n_in,
                              void* d_out, int out_size)
{
    const float* hidden = (const float*)d_in[0];
    const float* W_in   = (const float*)d_in[1];
    const float* conv_w = (const float*)d_in[2];
    const float* conv_b = (const float*)d_in[3];
    const float* W_x    = (const float*)d_in[4];
    const float* W_dt   = (const float*)d_in[5];
    const float* b_dt   = (const float*)d_in[6];
    const float* A_log  = (const float*)d_in[7];
    const float* D_skip = (const float*)d_in[8];
    const float* W_out  = (const float*)d_in[9];
    float* out = (float*)d_out;

    float *xz, *x, *xdbl, *delta, *y;
    cudaGetSymbolAddress((void**)&xz,    g_xz);
    cudaGetSymbolAddress((void**)&x,     g_x);
    cudaGetSymbolAddress((void**)&xdbl,  g_xdbl);
    cudaGetSymbolAddress((void**)&delta, g_delta);
    cudaGetSymbolAddress((void**)&y,     g_y);

    dim3 blk(256);

    // 1) xz = hidden @ W_in^T   (2048 x 8192, K=2048)
    tf32_gemm_nt<<<dim3((2*DINNER)/128, MROWS/128), blk>>>(
        hidden, DMODEL, W_in, DMODEL, xz, 2*DINNER,
        MROWS, 2*DINNER, DMODEL, 0, nullptr);

    // 2) causal conv + silu -> g_x
    conv_silu_kernel<<<dim3(DINNER/256, MROWS), 256>>>(conv_w, conv_b);

    // 3) x_dbl = x @ W_x^T      (2048 x 160, K=4096)
    tf32_gemm_nt<<<dim3((XDBL_W + 127)/128, MROWS/128), blk>>>(
        x, DINNER, W_x, DINNER, xdbl, XDBL_W,
        MROWS, XDBL_W, DINNER, 0, nullptr);

    // 4) delta = softplus(dt_low @ W_dt^T + b_dt)   (2048 x 4096, K=128)
    tf32_gemm_nt<<<dim3(DINNER/128, MROWS/128), blk>>>(
        xdbl, XDBL_W, W_dt, DTRANK, delta, DINNER,
        MROWS, DINNER, DTRANK, 1, b_dt);

    // 5) selective scan + skip + gating -> g_y
    scan_kernel<<<BATCH * (DINNER/64), 64>>>(A_log, D_skip);

    // 6) out = y @ W_out^T      (2048 x 2048, K=4096)
    tf32_gemm_nt<<<dim3(DMODEL/128, MROWS/128), blk>>>(
        y, DINNER, W_out, DINNER, out, DMODEL,
        MROWS, DMODEL, DINNER, 0, nullptr);
}

// round 4
// speedup vs baseline: 2.9122x; 1.2779x over previous
#include <cuda_runtime.h>
#include <cuda_bf16.h>
#include <math.h>
#include <stdint.h>

// ---------------- problem constants ----------------
#define BATCH    2
#define SEQ      1024
#define DMODEL   2048
#define DINNER   4096
#define DSTATE   16
#define DCONV    4
#define DTRANK   128
#define XDBL_W   (DTRANK + 2*DSTATE)   // 160
#define MROWS    (BATCH*SEQ)           // 2048
#define KSPLIT   8                     // split-K slices for x_dbl GEMM

// ---------------- device scratch ----------------
__device__ __align__(16) float g_xz   [(size_t)MROWS * (2*DINNER)];
__device__ __align__(16) float g_x    [(size_t)MROWS * DINNER];
__device__ __align__(16) float g_xdbl [(size_t)MROWS * XDBL_W];
__device__ __align__(16) float g_delta[(size_t)MROWS * DINNER];
__device__ __align__(16) float g_y    [(size_t)MROWS * DINNER];
__device__ __align__(16) float g_xpart[(size_t)KSPLIT * MROWS * XDBL_W];
// tf32-rounded operand copies
__device__ __align__(16) float g_hid_r [(size_t)MROWS * DMODEL];
__device__ __align__(16) float g_Win_r [(size_t)(2*DINNER) * DMODEL];
__device__ __align__(16) float g_Wx_r  [(size_t)XDBL_W * DINNER];
__device__ __align__(16) float g_Wdt_r [(size_t)DINNER * DTRANK];
__device__ __align__(16) float g_Wout_r[(size_t)DMODEL * DINNER];

// ---------------- helpers ----------------
__device__ __forceinline__ uint32_t smem_u32(const void* p) {
    uint32_t a;
    asm("{ .reg .u64 t; cvta.to.shared.u64 t, %1; cvt.u32.u64 %0, t; }" : "=r"(a) : "l"(p));
    return a;
}
__device__ __forceinline__ uint32_t f2tf32(float f) {
    uint32_t r; asm("cvt.rna.tf32.f32 %0, %1;" : "=r"(r) : "f"(f)); return r;
}
__device__ __forceinline__ float roundtf(float f) { return __uint_as_float(f2tf32(f)); }

__device__ __forceinline__ void cp16(uint32_t dst, const float* src, bool v) {
    int sz = v ? 16 : 0;  // src-size 0 -> zero-fill, no dereference
    asm volatile("cp.async.cg.shared.global [%0], [%1], 16, %2;"
                 :: "r"(dst), "l"(src), "r"(sz));
}
#define CP_COMMIT() asm volatile("cp.async.commit_group;" ::: "memory")

__device__ __forceinline__ void mma_tf32(float* c,
    uint32_t a0, uint32_t a1, uint32_t a2, uint32_t a3,
    uint32_t b0, uint32_t b1)
{
    asm volatile(
        "mma.sync.aligned.m16n8k8.row.col.f32.tf32.tf32.f32 "
        "{%0,%1,%2,%3}, {%4,%5,%6,%7}, {%8,%9}, {%0,%1,%2,%3};"
        : "+f"(c[0]), "+f"(c[1]), "+f"(c[2]), "+f"(c[3])
        : "r"(a0), "r"(a1), "r"(a2), "r"(a3), "r"(b0), "r"(b1));
}

// ---------------- TF32 GEMM with cp.async pipeline ----------------
// C[M,N] = A[M,K_total] * B[N,K_total]^T, K split over gridDim.z (Kslice per z).
// BM=BN=128, BK=16, 4-stage cp.async ring, 256 threads, warp tile 64x32.
// Inputs MUST already be tf32-rounded. Requires Kslice%16==0, Kslice>=48, M%128==0.
// smem stage: A 128 rows x stride-20 floats (80B) = 10240B, B same -> 20480B/stage.
// mode 0: plain store.  mode 1: softplus(acc + bias[col]).
#define GSMEM (4 * 20480)

__global__ __launch_bounds__(256, 2)
void tf32_gemm_cp(const float* __restrict__ A, int lda,
                  const float* __restrict__ B, int ldb,
                  float* __restrict__ C, int ldc,
                  int M, int N, int Kslice,
                  int mode, const float* __restrict__ bias,
                  size_t zstride)
{
    extern __shared__ float sm[];
    const uint32_t sb = smem_u32(sm);
    const int tid  = threadIdx.x;
    const int lane = tid & 31;
    const int w    = tid >> 5;
    const int wm   = (w & 1) * 64;
    const int wn   = (w >> 1) * 32;
    const int brow = blockIdx.y * 128;
    const int bcol = blockIdx.x * 128;
    const int kbeg = blockIdx.z * Kslice;
    const int lr = lane >> 2, lc = lane & 3;

    C += (size_t)blockIdx.z * zstride;

    float acc[4][4][4];
#pragma unroll
    for (int mt = 0; mt < 4; mt++)
#pragma unroll
        for (int nt = 0; nt < 4; nt++)
#pragma unroll
            for (int r = 0; r < 4; r++) acc[mt][nt][r] = 0.f;

    const int T = Kslice >> 4;
    const int crow = tid >> 2;       // 0..63
    const int cseg = tid & 3;        // 0..3

    auto issue = [&](int kc) {
        int kk = kbeg + (kc << 4);
        uint32_t st = sb + (uint32_t)(kc & 3) * 20480u;
#pragma unroll
        for (int j = 0; j < 2; j++) {
            int row = crow + 64 * j;
            cp16(st + row * 80 + cseg * 16,
                 A + (size_t)(brow + row) * lda + kk + cseg * 4, true);
        }
#pragma unroll
        for (int j = 0; j < 2; j++) {
            int row = crow + 64 * j;
            bool v = (bcol + row) < N;
            const float* src = B + (size_t)(v ? (bcol + row) : 0) * ldb + kk + cseg * 4;
            cp16(st + 10240 + row * 80 + cseg * 16, src, v);
        }
        CP_COMMIT();
    };

    issue(0); issue(1); issue(2);   // T >= 3 for all our shapes

    for (int kc = 0; kc < T; kc++) {
        // guarantee group kc complete (exact tail waits)
        if (kc < T - 2)      asm volatile("cp.async.wait_group 2;" ::: "memory");
        else if (kc == T - 2) asm volatile("cp.async.wait_group 1;" ::: "memory");
        else                 asm volatile("cp.async.wait_group 0;" ::: "memory");
        __syncthreads();

        if (kc + 3 < T) issue(kc + 3);

        const uint32_t* Sa = reinterpret_cast<const uint32_t*>(sm + (size_t)(kc & 3) * 5120);
        const uint32_t* Sb = Sa + 2560;

#pragma unroll
        for (int ks = 0; ks < 16; ks += 8) {
            uint32_t af[4][4], bf[4][2];
#pragma unroll
            for (int mt = 0; mt < 4; mt++) {
                int m0 = wm + mt * 16 + lr;
                af[mt][0] = Sa[m0 * 20 + ks + lc];
                af[mt][1] = Sa[(m0 + 8) * 20 + ks + lc];
                af[mt][2] = Sa[m0 * 20 + ks + 4 + lc];
                af[mt][3] = Sa[(m0 + 8) * 20 + ks + 4 + lc];
            }
#pragma unroll
            for (int nt = 0; nt < 4; nt++) {
                int n0 = wn + nt * 8 + lr;
                bf[nt][0] = Sb[n0 * 20 + ks + lc];
                bf[nt][1] = Sb[n0 * 20 + ks + 4 + lc];
            }
#pragma unroll
            for (int mt = 0; mt < 4; mt++)
#pragma unroll
                for (int nt = 0; nt < 4; nt++)
                    mma_tf32(acc[mt][nt], af[mt][0], af[mt][1], af[mt][2], af[mt][3],
                             bf[nt][0], bf[nt][1]);
        }
    }

    // ---- epilogue ----
#pragma unroll
    for (int mt = 0; mt < 4; mt++) {
#pragma unroll
        for (int nt = 0; nt < 4; nt++) {
#pragma unroll
            for (int r = 0; r < 4; r++) {
                int row = brow + wm + mt * 16 + lr + ((r & 2) ? 8 : 0);
                int col = bcol + wn + nt * 8 + 2 * lc + (r & 1);
                if (col >= N) continue;
                float v = acc[mt][nt][r];
                if (mode == 1) {
                    v += bias[col];
                    v = fmaxf(v, 0.f) + log1pf(expf(-fabsf(v)));
                }
                C[(size_t)row * ldc + col] = v;
            }
        }
    }
}

// ---------------- tf32 rounding prepass (float4) ----------------
__global__ void round_tf32_kernel(const float4* __restrict__ in,
                                  float4* __restrict__ out, int n4)
{
    int i = blockIdx.x * 256 + threadIdx.x;
    if (i < n4) {
        float4 v = in[i];
        v.x = roundtf(v.x); v.y = roundtf(v.y);
        v.z = roundtf(v.z); v.w = roundtf(v.w);
        out[i] = v;
    }
}

// ---------------- split-K reduction for x_dbl (+ round dt_low) ----------------
__global__ void reduce_xdbl_kernel()
{
    int i = blockIdx.x * 256 + threadIdx.x;
    if (i >= MROWS * XDBL_W) return;
    float s = 0.f;
#pragma unroll
    for (int z = 0; z < KSPLIT; z++)
        s += g_xpart[(size_t)z * MROWS * XDBL_W + i];
    int col = i % XDBL_W;
    if (col < DTRANK) s = roundtf(s);   // dt_low feeds the delta GEMM
    g_xdbl[i] = s;
}

// ---------------- causal depthwise conv1d (K=4) + SiLU (tf32-rounded out) ----------------
__global__ void conv_silu_kernel(const float* __restrict__ conv_w,
                                 const float* __restrict__ conv_b)
{
    int d = blockIdx.x * 256 + threadIdx.x;
    int m = blockIdx.y;
    int b = m >> 10;
    int l = m & (SEQ - 1);

    float acc = conv_b[d];
#pragma unroll
    for (int k = 0; k < DCONV; k++) {
        int lk = l - (DCONV - 1) + k;
        if (lk >= 0)
            acc = fmaf(conv_w[d * DCONV + k],
                       g_xz[(size_t)(b * SEQ + lk) * (2 * DINNER) + d], acc);
    }
    float s = acc / (1.f + __expf(-acc));
    g_x[(size_t)m * DINNER + d] = roundtf(s);   // x feeds x_dbl GEMM
}

// ---------------- selective scan, fused skip + gate (tf32-rounded out) ----------------
__global__ void scan_kernel(const float* __restrict__ A_log,
                            const float* __restrict__ D_skip)
{
    __shared__ float s_delta[32][64];
    __shared__ float s_u[32][64];
    __shared__ float s_z[32][64];
    __shared__ float s_bc[32][32];

    const int tid   = threadIdx.x;
    const int bpb   = DINNER / 64;
    const int b     = blockIdx.x / bpb;
    const int dbase = (blockIdx.x % bpb) * 64;
    const int d     = dbase + tid;

    float Arow[DSTATE];
#pragma unroll
    for (int n = 0; n < DSTATE; n++)
        Arow[n] = -__expf(A_log[(size_t)d * DSTATE + n]);
    const float Dv = D_skip[d];

    float h[DSTATE];
#pragma unroll
    for (int n = 0; n < DSTATE; n++) h[n] = 0.f;

    for (int l0 = 0; l0 < SEQ; l0 += 32) {
#pragma unroll 4
        for (int t = 0; t < 32; t++) {
            size_t row = (size_t)(b * SEQ + l0 + t);
            s_delta[t][tid] = g_delta[row * DINNER + d];
            s_u[t][tid]     = g_x[row * DINNER + d];
            s_z[t][tid]     = g_xz[row * (2 * DINNER) + DINNER + d];
        }
        for (int i = tid; i < 32 * 32; i += 64) {
            int t = i >> 5, j = i & 31;
            s_bc[t][j] = g_xdbl[(size_t)(b * SEQ + l0 + t) * XDBL_W + DTRANK + j];
        }
        __syncthreads();

        for (int t = 0; t < 32; t++) {
            float delta = s_delta[t][tid];
            float u     = s_u[t][tid];
            float du    = delta * u;
            float y     = 0.f;
#pragma unroll
            for (int n = 0; n < DSTATE; n++) {
                float dA = __expf(delta * Arow[n]);
                h[n] = fmaf(h[n], dA, du * s_bc[t][n]);
                y    = fmaf(h[n], s_bc[t][DSTATE + n], y);
            }
            float zz = s_z[t][tid];
            float gate = zz / (1.f + __expf(-zz));
            float out  = (y + Dv * u) * gate;
            g_y[(size_t)(b * SEQ + l0 + t) * DINNER + d] = roundtf(out);  // y feeds out GEMM
        }
        __syncthreads();
    }
}

// ---------------- launcher ----------------
extern "C" void kernel_launch(void* const* d_in, const int* in_sizes, int n_in,
                              void* d_out, int out_size)
{
    const float* hidden = (const float*)d_in[0];
    const float* W_in   = (const float*)d_in[1];
    const float* conv_w = (const float*)d_in[2];
    const float* conv_b = (const float*)d_in[3];
    const float* W_x    = (const float*)d_in[4];
    const float* W_dt   = (const float*)d_in[5];
    const float* b_dt   = (const float*)d_in[6];
    const float* A_log  = (const float*)d_in[7];
    const float* D_skip = (const float*)d_in[8];
    const float* W_out  = (const float*)d_in[9];
    float* out = (float*)d_out;

    float *xz, *x, *xdbl, *delta, *y, *xpart;
    float *hid_r, *Win_r, *Wx_r, *Wdt_r, *Wout_r;
    cudaGetSymbolAddress((void**)&xz,    g_xz);
    cudaGetSymbolAddress((void**)&x,     g_x);
    cudaGetSymbolAddress((void**)&xdbl,  g_xdbl);
    cudaGetSymbolAddress((void**)&delta, g_delta);
    cudaGetSymbolAddress((void**)&y,     g_y);
    cudaGetSymbolAddress((void**)&xpart, g_xpart);
    cudaGetSymbolAddress((void**)&hid_r, g_hid_r);
    cudaGetSymbolAddress((void**)&Win_r, g_Win_r);
    cudaGetSymbolAddress((void**)&Wx_r,  g_Wx_r);
    cudaGetSymbolAddress((void**)&Wdt_r, g_Wdt_r);
    cudaGetSymbolAddress((void**)&Wout_r, g_Wout_r);

    cudaFuncSetAttribute(tf32_gemm_cp, cudaFuncAttributeMaxDynamicSharedMemorySize, GSMEM);

    // 0) tf32-round static GEMM operands
    {
        int n;
        n = MROWS * DMODEL / 4;
        round_tf32_kernel<<<(n + 255) / 256, 256>>>((const float4*)hidden, (float4*)hid_r, n);
        n = (2 * DINNER) * DMODEL / 4;
        round_tf32_kernel<<<(n + 255) / 256, 256>>>((const float4*)W_in, (float4*)Win_r, n);
        n = XDBL_W * DINNER / 4;
        round_tf32_kernel<<<(n + 255) / 256, 256>>>((const float4*)W_x, (float4*)Wx_r, n);
        n = DINNER * DTRANK / 4;
        round_tf32_kernel<<<(n + 255) / 256, 256>>>((const float4*)W_dt, (float4*)Wdt_r, n);
        n = DMODEL * DINNER / 4;
        round_tf32_kernel<<<(n + 255) / 256, 256>>>((const float4*)W_out, (float4*)Wout_r, n);
    }

    // 1) xz = hidden @ W_in^T   (2048 x 8192, K=2048)
    tf32_gemm_cp<<<dim3((2*DINNER)/128, MROWS/128, 1), 256, GSMEM>>>(
        hid_r, DMODEL, Win_r, DMODEL, xz, 2*DINNER,
        MROWS, 2*DINNER, DMODEL, 0, nullptr, 0);

    // 2) causal conv + silu -> g_x
    conv_silu_kernel<<<dim3(DINNER/256, MROWS), 256>>>(conv_w, conv_b);

    // 3) x_dbl partials: (2048 x 160, K=4096) split-K over 8 slices
    tf32_gemm_cp<<<dim3(2, MROWS/128, KSPLIT), 256, GSMEM>>>(
        x, DINNER, Wx_r, DINNER, xpart, XDBL_W,
        MROWS, XDBL_W, DINNER / KSPLIT, 0, nullptr,
        (size_t)MROWS * XDBL_W);
    reduce_xdbl_kernel<<<(MROWS * XDBL_W + 255) / 256, 256>>>();

    // 4) delta = softplus(dt_low @ W_dt^T + b_dt)   (2048 x 4096, K=128)
    tf32_gemm_cp<<<dim3(DINNER/128, MROWS/128, 1), 256, GSMEM>>>(
        xdbl, XDBL_W, Wdt_r, DTRANK, delta, DINNER,
        MROWS, DINNER, DTRANK, 1, b_dt, 0);

    // 5) selective scan + skip + gating -> g_y
    scan_kernel<<<BATCH * (DINNER/64), 64>>>(A_log, D_skip);

    // 6) out = y @ W_out^T      (2048 x 2048, K=4096)
    tf32_gemm_cp<<<dim3(DMODEL/128, MROWS/128, 1), 256, GSMEM>>>(
        y, DINNER, Wout_r, DINNER, out, DMODEL,
        MROWS, DMODEL, DINNER, 0, nullptr, 0);
}